// round 1
// baseline (speedup 1.0000x reference)
#include <cuda_runtime.h>

// Problem constants (fixed by the dataset)
#define CS   256            // S
#define CN   558            // N
#define CB2  8192           // B2 (power of 2)
#define CF   128            // F_IN == F_OUT
#define CM   (CS * CN)      // 142848 nodes
#define CE   (CS * CB2)     // 2097152 edges

// ---------------------------------------------------------------------------
// Scratch (device globals; no allocation allowed in kernel_launch)
// ---------------------------------------------------------------------------
__device__ float    g_agg[(size_t)CM * CF];   // aggregated features (M x F), ~73 MB
__device__ float    g_deg[CM];
__device__ float    g_dinv[CM];
__device__ unsigned g_bdmax_bits;

// ---------------------------------------------------------------------------
// 1) init: deg = 1.0 (self loop), bdmax = 0
// ---------------------------------------------------------------------------
__global__ void k_init() {
    int i = blockIdx.x * blockDim.x + threadIdx.x;
    if (i == 0) g_bdmax_bits = 0u;
    if (i < CM) g_deg[i] = 1.0f;
}

// ---------------------------------------------------------------------------
// 2) bd_max = max over masked bond_dist  (positive floats: uint bits monotone)
// ---------------------------------------------------------------------------
__global__ void k_bdmax(const int* __restrict__ ei, const float* __restrict__ bd) {
    float v = 0.0f;
    int stride = gridDim.x * blockDim.x;
    for (int g = blockIdx.x * blockDim.x + threadIdx.x; g < CE; g += stride) {
        int s   = g >> 13;              // / B2
        int e   = g & (CB2 - 1);
        int src = __ldg(&ei[(size_t)s * 2 * CB2 + e]);
        int dst = __ldg(&ei[(size_t)s * 2 * CB2 + CB2 + e]);
        if (src != dst) v = fmaxf(v, __ldg(&bd[g]));
    }
    #pragma unroll
    for (int o = 16; o > 0; o >>= 1)
        v = fmaxf(v, __shfl_xor_sync(0xffffffffu, v, o));
    __shared__ float sm[32];
    int lane = threadIdx.x & 31, wid = threadIdx.x >> 5;
    if (lane == 0) sm[wid] = v;
    __syncthreads();
    if (wid == 0) {
        v = (lane < (int)(blockDim.x >> 5)) ? sm[lane] : 0.0f;
        #pragma unroll
        for (int o = 16; o > 0; o >>= 1)
            v = fmaxf(v, __shfl_xor_sync(0xffffffffu, v, o));
        if (lane == 0) atomicMax(&g_bdmax_bits, __float_as_uint(v));
    }
}

// ---------------------------------------------------------------------------
// 3) deg[col] += w  for valid edges
// ---------------------------------------------------------------------------
__global__ void k_deg(const int* __restrict__ ei, const float* __restrict__ bd) {
    int g = blockIdx.x * blockDim.x + threadIdx.x;
    if (g >= CE) return;
    int s   = g >> 13;
    int e   = g & (CB2 - 1);
    int src = __ldg(&ei[(size_t)s * 2 * CB2 + e]);
    int dst = __ldg(&ei[(size_t)s * 2 * CB2 + CB2 + e]);
    if (src == dst) return;
    float bm = __uint_as_float(g_bdmax_bits);
    float w  = __ldg(&bd[g]) / bm;
    atomicAdd(&g_deg[s * CN + dst], w);
}

// ---------------------------------------------------------------------------
// 4) dinv = rsqrt(deg)   (deg >= 1 always, matches deg>0 guard)
// ---------------------------------------------------------------------------
__global__ void k_dinv() {
    int i = blockIdx.x * blockDim.x + threadIdx.x;
    if (i < CM) g_dinv[i] = rsqrtf(g_deg[i]);
}

// ---------------------------------------------------------------------------
// 5) self-loop init: agg[i,:] = dinv[i]^2 * x[i,:]
// ---------------------------------------------------------------------------
__global__ void k_selfloop(const float* __restrict__ x) {
    int i4 = blockIdx.x * blockDim.x + threadIdx.x;      // over M * F/4
    if (i4 >= CM * (CF / 4)) return;
    int node = i4 >> 5;                                  // / (F/4 = 32)
    float d = g_dinv[node];
    float c = d * d;
    float4 xv = __ldg(((const float4*)x) + i4);
    float4 r;
    r.x = c * xv.x; r.y = c * xv.y; r.z = c * xv.z; r.w = c * xv.w;
    ((float4*)g_agg)[i4] = r;
}

// ---------------------------------------------------------------------------
// 6) edge scatter: one warp per edge, vectorized global reduction
//    agg[col,:] += dinv[row]*w*dinv[col] * x[row,:]
// ---------------------------------------------------------------------------
__global__ void k_scatter(const int* __restrict__ ei, const float* __restrict__ bd,
                          const float* __restrict__ x) {
    int g    = (blockIdx.x * blockDim.x + threadIdx.x) >> 5;  // warp id = edge id
    int lane = threadIdx.x & 31;
    if (g >= CE) return;
    int s   = g >> 13;
    int e   = g & (CB2 - 1);
    int src = __ldg(&ei[(size_t)s * 2 * CB2 + e]);
    int dst = __ldg(&ei[(size_t)s * 2 * CB2 + CB2 + e]);
    if (src == dst) return;                               // masked / padded
    int row = s * CN + src;
    int col = s * CN + dst;
    float bm   = __uint_as_float(g_bdmax_bits);
    float coef = g_dinv[row] * (__ldg(&bd[g]) / bm) * g_dinv[col];
    float4 v = __ldg(((const float4*)(x + (size_t)row * CF)) + lane);
    float* dp = g_agg + (size_t)col * CF + lane * 4;
    asm volatile("red.global.add.v4.f32 [%0], {%1, %2, %3, %4};"
                 :: "l"(dp), "f"(v.x * coef), "f"(v.y * coef),
                    "f"(v.z * coef), "f"(v.w * coef)
                 : "memory");
}

// ---------------------------------------------------------------------------
// 7) out = agg @ W^T + bias    (M x 128) @ (128 x 128)
//    Tiled fp32 SGEMM: BM=BN=128, BK=16, 8x8 per thread, 256 threads.
// ---------------------------------------------------------------------------
#define BM 128
#define BN 128
#define BK 16
__global__ void __launch_bounds__(256) k_gemm(const float* __restrict__ Wm,
                                              const float* __restrict__ bias,
                                              float* __restrict__ out) {
    __shared__ float As[BK][BM + 1];   // As[k][m]
    __shared__ float Bs[BK][BN + 1];   // Bs[k][n] = W[n][k]
    int tid = threadIdx.x;
    int m0  = blockIdx.x * BM;
    int trow = tid >> 4;               // 0..15
    int tcol = tid & 15;               // 0..15

    float acc[8][8];
    #pragma unroll
    for (int i = 0; i < 8; i++)
        #pragma unroll
        for (int j = 0; j < 8; j++) acc[i][j] = 0.0f;

    const float* A = g_agg + (size_t)m0 * CF;

    for (int k0 = 0; k0 < CF; k0 += BK) {
        // Load A chunk: 128 rows x 16 cols = 512 float4s, 2 per thread
        #pragma unroll
        for (int t = 0; t < 2; t++) {
            int idx = tid + t * 256;       // 0..511
            int r   = idx >> 2;            // row 0..127
            int c4  = idx & 3;             // float4 index within 16 cols
            float4 v = *(const float4*)(A + (size_t)r * CF + k0 + c4 * 4);
            As[c4 * 4 + 0][r] = v.x;
            As[c4 * 4 + 1][r] = v.y;
            As[c4 * 4 + 2][r] = v.z;
            As[c4 * 4 + 3][r] = v.w;
        }
        // Load W chunk: Bs[k][n] = W[n][k0+k]
        #pragma unroll
        for (int t = 0; t < 2; t++) {
            int idx = tid + t * 256;
            int n   = idx >> 2;
            int c4  = idx & 3;
            float4 v = *(const float4*)(Wm + (size_t)n * CF + k0 + c4 * 4);
            Bs[c4 * 4 + 0][n] = v.x;
            Bs[c4 * 4 + 1][n] = v.y;
            Bs[c4 * 4 + 2][n] = v.z;
            Bs[c4 * 4 + 3][n] = v.w;
        }
        __syncthreads();
        #pragma unroll
        for (int k = 0; k < BK; k++) {
            float a[8], b[8];
            #pragma unroll
            for (int i = 0; i < 8; i++) a[i] = As[k][i * 16 + trow];  // broadcast
            #pragma unroll
            for (int j = 0; j < 8; j++) b[j] = Bs[k][j * 16 + tcol];  // conflict-free
            #pragma unroll
            for (int i = 0; i < 8; i++)
                #pragma unroll
                for (int j = 0; j < 8; j++)
                    acc[i][j] += a[i] * b[j];
        }
        __syncthreads();
    }

    float bv[8];
    #pragma unroll
    for (int j = 0; j < 8; j++) bv[j] = __ldg(&bias[j * 16 + tcol]);

    #pragma unroll
    for (int i = 0; i < 8; i++) {
        int r = m0 + i * 16 + trow;
        #pragma unroll
        for (int j = 0; j < 8; j++) {
            out[(size_t)r * CF + j * 16 + tcol] = acc[i][j] + bv[j];
        }
    }
}

// ---------------------------------------------------------------------------
// Launch
// ---------------------------------------------------------------------------
extern "C" void kernel_launch(void* const* d_in, const int* in_sizes, int n_in,
                              void* d_out, int out_size) {
    const float* x    = (const float*)d_in[0];   // (S, N, 128) f32
    const int*   ei   = (const int*)d_in[1];     // (S, 2, B2) i32
    const float* bd   = (const float*)d_in[2];   // (S, B2) f32
    const float* Wm   = (const float*)d_in[3];   // (128, 128) f32
    const float* bias = (const float*)d_in[4];   // (128,) f32
    float*       out  = (float*)d_out;           // (M, 128) f32

    (void)in_sizes; (void)n_in; (void)out_size;

    k_init<<<(CM + 255) / 256, 256>>>();
    k_bdmax<<<1024, 256>>>(ei, bd);
    k_deg<<<(CE + 255) / 256, 256>>>(ei, bd);
    k_dinv<<<(CM + 255) / 256, 256>>>();
    k_selfloop<<<((CM * (CF / 4)) + 255) / 256, 256>>>(x);
    // one warp per edge: CE warps, 8 warps (256 threads) per block
    k_scatter<<<CE / 8, 256>>>(ei, bd, x);
    k_gemm<<<CM / BM, 256>>>(Wm, bias, out);
}

// round 2
// speedup vs baseline: 2.0394x; 2.0394x over previous
#include <cuda_runtime.h>

// Problem constants (fixed by the dataset)
#define CS   256            // S
#define CN   558            // N
#define CB2  8192           // B2 (power of 2)
#define CF   128            // F_IN == F_OUT
#define CM   (CS * CN)      // 142848 nodes
#define CE   (CS * CB2)     // 2097152 edges
#define CAP  128            // CSR capacity per destination node (in-degree ~11)

// ---------------------------------------------------------------------------
// Scratch (device globals; no allocation allowed in kernel_launch)
// ---------------------------------------------------------------------------
__device__ float    g_xw[(size_t)CM * CF];      // X @ W^T   (~73 MB)
__device__ float    g_deg[CM];
__device__ float    g_dinv[CM];
__device__ int      g_cnt[CM];
__device__ int2     g_rec[(size_t)CM * CAP];    // {row, bits(w*dinv[row])}  (~146 MB)
__device__ unsigned g_bdmax_bits;

// ---------------------------------------------------------------------------
// 1) init: deg = 1.0 (self loop), cnt = 0, bdmax = 0
// ---------------------------------------------------------------------------
__global__ void k_init() {
    int i = blockIdx.x * blockDim.x + threadIdx.x;
    if (i == 0) g_bdmax_bits = 0u;
    if (i < CM) { g_deg[i] = 1.0f; g_cnt[i] = 0; }
}

// ---------------------------------------------------------------------------
// 2) bd_max = max over valid bond_dist (positive floats: uint bits monotone)
// ---------------------------------------------------------------------------
__global__ void k_bdmax(const int* __restrict__ ei, const float* __restrict__ bd) {
    float v = 0.0f;
    int stride = gridDim.x * blockDim.x;
    for (int g = blockIdx.x * blockDim.x + threadIdx.x; g < CE; g += stride) {
        int s   = g >> 13;
        int e   = g & (CB2 - 1);
        int src = __ldg(&ei[(size_t)s * 2 * CB2 + e]);
        int dst = __ldg(&ei[(size_t)s * 2 * CB2 + CB2 + e]);
        if (src != dst) v = fmaxf(v, __ldg(&bd[g]));
    }
    #pragma unroll
    for (int o = 16; o > 0; o >>= 1)
        v = fmaxf(v, __shfl_xor_sync(0xffffffffu, v, o));
    __shared__ float sm[32];
    int lane = threadIdx.x & 31, wid = threadIdx.x >> 5;
    if (lane == 0) sm[wid] = v;
    __syncthreads();
    if (wid == 0) {
        v = (lane < (int)(blockDim.x >> 5)) ? sm[lane] : 0.0f;
        #pragma unroll
        for (int o = 16; o > 0; o >>= 1)
            v = fmaxf(v, __shfl_xor_sync(0xffffffffu, v, o));
        if (lane == 0) atomicMax(&g_bdmax_bits, __float_as_uint(v));
    }
}

// ---------------------------------------------------------------------------
// 3) deg[col] += w   for valid edges
// ---------------------------------------------------------------------------
__global__ void k_deg(const int* __restrict__ ei, const float* __restrict__ bd) {
    int g = blockIdx.x * blockDim.x + threadIdx.x;
    if (g >= CE) return;
    int s   = g >> 13;
    int e   = g & (CB2 - 1);
    int src = __ldg(&ei[(size_t)s * 2 * CB2 + e]);
    int dst = __ldg(&ei[(size_t)s * 2 * CB2 + CB2 + e]);
    if (src == dst) return;
    float bm = __uint_as_float(g_bdmax_bits);
    atomicAdd(&g_deg[s * CN + dst], __ldg(&bd[g]) / bm);
}

// ---------------------------------------------------------------------------
// 4) dinv = rsqrt(deg)   (deg >= 1 always, matches deg>0 guard)
// ---------------------------------------------------------------------------
__global__ void k_dinv() {
    int i = blockIdx.x * blockDim.x + threadIdx.x;
    if (i < CM) g_dinv[i] = rsqrtf(g_deg[i]);
}

// ---------------------------------------------------------------------------
// 5) fill CSR: rec[col][idx] = { row, w * dinv[row] }
// ---------------------------------------------------------------------------
__global__ void k_fill(const int* __restrict__ ei, const float* __restrict__ bd) {
    int g = blockIdx.x * blockDim.x + threadIdx.x;
    if (g >= CE) return;
    int s   = g >> 13;
    int e   = g & (CB2 - 1);
    int src = __ldg(&ei[(size_t)s * 2 * CB2 + e]);
    int dst = __ldg(&ei[(size_t)s * 2 * CB2 + CB2 + e]);
    if (src == dst) return;
    int row = s * CN + src;
    int col = s * CN + dst;
    float bm = __uint_as_float(g_bdmax_bits);
    float w2 = (__ldg(&bd[g]) / bm) * g_dinv[row];
    int idx = atomicAdd(&g_cnt[col], 1);
    if (idx < CAP)
        g_rec[(size_t)col * CAP + idx] = make_int2(row, __float_as_int(w2));
}

// ---------------------------------------------------------------------------
// 6) xw = x @ W^T   (M x 128) @ (128 x 128), fp32, bias deferred
// ---------------------------------------------------------------------------
#define BM 128
#define BN 128
#define BK 16
__global__ void __launch_bounds__(256) k_gemm(const float* __restrict__ A,
                                              const float* __restrict__ Wm) {
    __shared__ float As[BK][BM + 1];
    __shared__ float Bs[BK][BN + 1];
    int tid = threadIdx.x;
    int m0  = blockIdx.x * BM;
    int trow = tid >> 4;
    int tcol = tid & 15;

    float acc[8][8];
    #pragma unroll
    for (int i = 0; i < 8; i++)
        #pragma unroll
        for (int j = 0; j < 8; j++) acc[i][j] = 0.0f;

    const float* Ab = A + (size_t)m0 * CF;

    for (int k0 = 0; k0 < CF; k0 += BK) {
        #pragma unroll
        for (int t = 0; t < 2; t++) {
            int idx = tid + t * 256;
            int r   = idx >> 2;
            int c4  = idx & 3;
            float4 v = *(const float4*)(Ab + (size_t)r * CF + k0 + c4 * 4);
            As[c4 * 4 + 0][r] = v.x;
            As[c4 * 4 + 1][r] = v.y;
            As[c4 * 4 + 2][r] = v.z;
            As[c4 * 4 + 3][r] = v.w;
        }
        #pragma unroll
        for (int t = 0; t < 2; t++) {
            int idx = tid + t * 256;
            int n   = idx >> 2;
            int c4  = idx & 3;
            float4 v = *(const float4*)(Wm + (size_t)n * CF + k0 + c4 * 4);
            Bs[c4 * 4 + 0][n] = v.x;
            Bs[c4 * 4 + 1][n] = v.y;
            Bs[c4 * 4 + 2][n] = v.z;
            Bs[c4 * 4 + 3][n] = v.w;
        }
        __syncthreads();
        #pragma unroll
        for (int k = 0; k < BK; k++) {
            float a[8], b[8];
            #pragma unroll
            for (int i = 0; i < 8; i++) a[i] = As[k][i * 16 + trow];
            #pragma unroll
            for (int j = 0; j < 8; j++) b[j] = Bs[k][j * 16 + tcol];
            #pragma unroll
            for (int i = 0; i < 8; i++)
                #pragma unroll
                for (int j = 0; j < 8; j++)
                    acc[i][j] += a[i] * b[j];
        }
        __syncthreads();
    }

    #pragma unroll
    for (int i = 0; i < 8; i++) {
        int r = m0 + i * 16 + trow;
        #pragma unroll
        for (int j = 0; j < 8; j++)
            g_xw[(size_t)r * CF + j * 16 + tcol] = acc[i][j];
    }
}

// ---------------------------------------------------------------------------
// 7) gather: out[col] = dinv[col] * ( dinv[col]*xw[col] + Σ w2*xw[row] ) + bias
//    One warp per node. Lane L owns float4 features [4L, 4L+4).
// ---------------------------------------------------------------------------
__global__ void __launch_bounds__(256) k_agg(const float* __restrict__ bias,
                                             float* __restrict__ out) {
    int wg   = (blockIdx.x * blockDim.x + threadIdx.x) >> 5;  // node id
    int lane = threadIdx.x & 31;
    if (wg >= CM) return;

    const float4* xw4 = (const float4*)g_xw;
    float dc  = g_dinv[wg];
    int   deg = min(g_cnt[wg], CAP);

    float4 xv = __ldg(xw4 + (size_t)wg * 32 + lane);
    float4 acc;
    acc.x = dc * xv.x; acc.y = dc * xv.y; acc.z = dc * xv.z; acc.w = dc * xv.w;

    const int2* r = g_rec + (size_t)wg * CAP;
    for (int e0 = 0; e0 < deg; e0 += 32) {
        int idx = e0 + lane;
        int2 rc = make_int2(0, 0);
        if (idx < deg) rc = __ldg(r + idx);
        int nv = min(32, deg - e0);
        for (int j = 0; j < nv; j++) {
            int   row = __shfl_sync(0xffffffffu, rc.x, j);
            float w2  = __int_as_float(__shfl_sync(0xffffffffu, rc.y, j));
            float4 v  = __ldg(xw4 + (size_t)row * 32 + lane);
            acc.x += w2 * v.x; acc.y += w2 * v.y;
            acc.z += w2 * v.z; acc.w += w2 * v.w;
        }
    }

    float4 b4 = __ldg(((const float4*)bias) + lane);
    float4 o;
    o.x = dc * acc.x + b4.x;
    o.y = dc * acc.y + b4.y;
    o.z = dc * acc.z + b4.z;
    o.w = dc * acc.w + b4.w;
    ((float4*)out)[(size_t)wg * 32 + lane] = o;
}

// ---------------------------------------------------------------------------
// Launch
// ---------------------------------------------------------------------------
extern "C" void kernel_launch(void* const* d_in, const int* in_sizes, int n_in,
                              void* d_out, int out_size) {
    const float* x    = (const float*)d_in[0];   // (S, N, 128) f32
    const int*   ei   = (const int*)d_in[1];     // (S, 2, B2) i32
    const float* bd   = (const float*)d_in[2];   // (S, B2) f32
    const float* Wm   = (const float*)d_in[3];   // (128, 128) f32
    const float* bias = (const float*)d_in[4];   // (128,) f32
    float*       out  = (float*)d_out;           // (M, 128) f32

    (void)in_sizes; (void)n_in; (void)out_size;

    k_init<<<(CM + 255) / 256, 256>>>();
    k_bdmax<<<1024, 256>>>(ei, bd);
    k_deg<<<(CE + 255) / 256, 256>>>(ei, bd);
    k_dinv<<<(CM + 255) / 256, 256>>>();
    k_fill<<<(CE + 255) / 256, 256>>>(ei, bd);
    k_gemm<<<CM / BM, 256>>>(x, Wm);
    k_agg<<<(CM * 32 + 255) / 256, 256>>>(bias, out);
}

// round 4
// speedup vs baseline: 2.1409x; 1.0497x over previous
#include <cuda_runtime.h>
#include <cuda_bf16.h>
#include <cstdint>

// Problem constants (fixed by the dataset)
#define CS   256
#define CN   558
#define CB2  8192
#define CF   128
#define CM   (CS * CN)      // 142848
#define CE   (CS * CB2)     // 2097152
#define CAP  128            // CSR capacity per destination (in-degree ~11)

// ---------------------------------------------------------------------------
// Scratch
// ---------------------------------------------------------------------------
__device__ float    g_xw[(size_t)CM * CF];
__device__ float    g_deg[CM];                 // raw sum of bd over in-edges
__device__ float    g_dinv[CM];
__device__ int      g_cnt[CM];
__device__ int2     g_rec[(size_t)CM * CAP];   // {row, bits(bd)}
__device__ unsigned g_bdmax_bits;

// ---------------------------------------------------------------------------
// 1) init
// ---------------------------------------------------------------------------
__global__ void k_init() {
    int i = blockIdx.x * blockDim.x + threadIdx.x;
    if (i == 0) g_bdmax_bits = 0u;
    if (i < CM) { g_deg[i] = 0.0f; g_cnt[i] = 0; }
}

// ---------------------------------------------------------------------------
// 2) bd_max over valid edges (positive floats: uint bits monotone)
// ---------------------------------------------------------------------------
__global__ void k_bdmax(const int* __restrict__ ei, const float* __restrict__ bd) {
    float v = 0.0f;
    int stride = gridDim.x * blockDim.x;
    for (int g = blockIdx.x * blockDim.x + threadIdx.x; g < CE; g += stride) {
        int s   = g >> 13;
        int e   = g & (CB2 - 1);
        int src = __ldg(&ei[(size_t)s * 2 * CB2 + e]);
        int dst = __ldg(&ei[(size_t)s * 2 * CB2 + CB2 + e]);
        if (src != dst) v = fmaxf(v, __ldg(&bd[g]));
    }
    #pragma unroll
    for (int o = 16; o > 0; o >>= 1)
        v = fmaxf(v, __shfl_xor_sync(0xffffffffu, v, o));
    __shared__ float sm[32];
    int lane = threadIdx.x & 31, wid = threadIdx.x >> 5;
    if (lane == 0) sm[wid] = v;
    __syncthreads();
    if (wid == 0) {
        v = (lane < (int)(blockDim.x >> 5)) ? sm[lane] : 0.0f;
        #pragma unroll
        for (int o = 16; o > 0; o >>= 1)
            v = fmaxf(v, __shfl_xor_sync(0xffffffffu, v, o));
        if (lane == 0) atomicMax(&g_bdmax_bits, __float_as_uint(v));
    }
}

// ---------------------------------------------------------------------------
// 3) fused: deg[col] += bd ; CSR fill rec[col] = {row, bd}
// ---------------------------------------------------------------------------
__global__ void k_build(const int* __restrict__ ei, const float* __restrict__ bd) {
    int g = blockIdx.x * blockDim.x + threadIdx.x;
    if (g >= CE) return;
    int s   = g >> 13;
    int e   = g & (CB2 - 1);
    int src = __ldg(&ei[(size_t)s * 2 * CB2 + e]);
    int dst = __ldg(&ei[(size_t)s * 2 * CB2 + CB2 + e]);
    if (src == dst) return;
    int row = s * CN + src;
    int col = s * CN + dst;
    float bdv = __ldg(&bd[g]);
    atomicAdd(&g_deg[col], bdv);
    int idx = atomicAdd(&g_cnt[col], 1);
    if (idx < CAP)
        g_rec[(size_t)col * CAP + idx] = make_int2(row, __float_as_int(bdv));
}

// ---------------------------------------------------------------------------
// 4) dinv = rsqrt(1 + deg/bd_max)
// ---------------------------------------------------------------------------
__global__ void k_dinv() {
    int i = blockIdx.x * blockDim.x + threadIdx.x;
    if (i >= CM) return;
    float bm = __uint_as_float(g_bdmax_bits);
    g_dinv[i] = rsqrtf(1.0f + g_deg[i] / bm);
}

// ---------------------------------------------------------------------------
// 5) xw = x @ W^T via mma.sync bf16 (3-term hi/lo split)
//    CTA = 128 rows, 8 warps, warp = 16 rows x 128 cols.
//    Smem planes: Ah, Al, Wh, Wl, each 128x128 bf16 (32KB), XOR-swizzled.
// ---------------------------------------------------------------------------
__device__ __forceinline__ unsigned smem_u32(const void* p) {
    unsigned a;
    asm("{ .reg .u64 t; cvta.to.shared.u64 t, %1; cvt.u32.u64 %0, t; }" : "=r"(a) : "l"(p));
    return a;
}
__device__ __forceinline__ uint4 ldsm4(unsigned addr) {
    uint4 v;
    asm volatile("ldmatrix.sync.aligned.m8n8.x4.shared.b16 {%0,%1,%2,%3}, [%4];"
                 : "=r"(v.x), "=r"(v.y), "=r"(v.z), "=r"(v.w) : "r"(addr));
    return v;
}
__device__ __forceinline__ void mma_bf16(float* d, uint4 a, unsigned b0, unsigned b1) {
    asm volatile(
        "mma.sync.aligned.m16n8k16.row.col.f32.bf16.bf16.f32 "
        "{%0,%1,%2,%3}, {%4,%5,%6,%7}, {%8,%9}, {%0,%1,%2,%3};"
        : "+f"(d[0]), "+f"(d[1]), "+f"(d[2]), "+f"(d[3])
        : "r"(a.x), "r"(a.y), "r"(a.z), "r"(a.w), "r"(b0), "r"(b1));
}

// swizzled byte offset within a 128x128-bf16 plane (256B rows, 16B chunks)
__device__ __forceinline__ int swz(int r, int chunk) {
    return r * 256 + ((chunk ^ (r & 7)) << 4);
}

__device__ __forceinline__ void conv_tile(char* th, char* tl,
                                          const float* __restrict__ g, int tid) {
    for (int p = tid; p < 128 * 64; p += 256) {
        int r  = p >> 6;
        int kp = p & 63;                       // pair index (2 bf16 = 4B)
        float2 f = __ldg((const float2*)g + (size_t)r * 64 + kp);
        __nv_bfloat16 h0 = __float2bfloat16_rn(f.x);
        __nv_bfloat16 h1 = __float2bfloat16_rn(f.y);
        __nv_bfloat16 l0 = __float2bfloat16_rn(f.x - __bfloat162float(h0));
        __nv_bfloat16 l1 = __float2bfloat16_rn(f.y - __bfloat162float(h1));
        unsigned hh = ((unsigned)__bfloat16_as_ushort(h1) << 16) | __bfloat16_as_ushort(h0);
        unsigned ll = ((unsigned)__bfloat16_as_ushort(l1) << 16) | __bfloat16_as_ushort(l0);
        int byte = swz(r, kp >> 2) + ((kp & 3) << 2);
        *(unsigned*)(th + byte) = hh;
        *(unsigned*)(tl + byte) = ll;
    }
}

#define SM_AH 0
#define SM_AL 32768
#define SM_WH 65536
#define SM_WL 98304
#define SM_TOT 131072

__global__ void __launch_bounds__(256) k_gemm(const float* __restrict__ x,
                                              const float* __restrict__ Wm) {
    extern __shared__ char smem[];
    int tid = threadIdx.x, wid = tid >> 5, lane = tid & 31;
    size_t m0 = (size_t)blockIdx.x * 128;

    conv_tile(smem + SM_AH, smem + SM_AL, x + m0 * CF, tid);
    conv_tile(smem + SM_WH, smem + SM_WL, Wm, tid);
    __syncthreads();

    unsigned sAh = smem_u32(smem + SM_AH);
    unsigned sAl = smem_u32(smem + SM_AL);
    unsigned sWh = smem_u32(smem + SM_WH);
    unsigned sWl = smem_u32(smem + SM_WL);

    int rbase = wid * 16;
    float acc[16][4];
    #pragma unroll
    for (int j = 0; j < 16; j++)
        #pragma unroll
        for (int c = 0; c < 4; c++) acc[j][c] = 0.0f;

    // A fragment address: matrix m = lane>>3 -> row rbase+(m&1)*8+(lane&7),
    //                     chunk ks*2+(m>>1)
    int am = lane >> 3;
    int ar = rbase + ((am & 1) << 3) + (lane & 7);
    int ac_off = am >> 1;
    // B fragment address (x4 load i): m = lane>>3 -> row 16i+(m>>1)*8+(lane&7),
    //                     chunk ks*2+(m&1)
    int bm = lane >> 3;
    int br_off = ((bm >> 1) << 3) + (lane & 7);
    int bc_off = bm & 1;

    #pragma unroll
    for (int ks = 0; ks < 8; ks++) {
        uint4 ah = ldsm4(sAh + swz(ar, ks * 2 + ac_off));
        uint4 al = ldsm4(sAl + swz(ar, ks * 2 + ac_off));
        #pragma unroll
        for (int i = 0; i < 8; i++) {
            int brow = i * 16 + br_off;
            uint4 bh = ldsm4(sWh + swz(brow, ks * 2 + bc_off));
            mma_bf16(acc[2 * i],     ah, bh.x, bh.y);
            mma_bf16(acc[2 * i + 1], ah, bh.z, bh.w);
            mma_bf16(acc[2 * i],     al, bh.x, bh.y);
            mma_bf16(acc[2 * i + 1], al, bh.z, bh.w);
            uint4 bl = ldsm4(sWl + swz(brow, ks * 2 + bc_off));
            mma_bf16(acc[2 * i],     ah, bl.x, bl.y);
            mma_bf16(acc[2 * i + 1], ah, bl.z, bl.w);
        }
    }

    // Epilogue: D fragment -> g_xw. d0,d1 at (row=t/4, col=8j+2(t%4)), d2,d3 at row+8.
    int erow = rbase + (lane >> 2);
    int ecol = (lane & 3) * 2;
    #pragma unroll
    for (int j = 0; j < 16; j++) {
        float* p0 = g_xw + (m0 + erow) * CF + j * 8 + ecol;
        p0[0] = acc[j][0];
        p0[1] = acc[j][1];
        float* p1 = p0 + 8 * CF;
        p1[0] = acc[j][2];
        p1[1] = acc[j][3];
    }
}

// ---------------------------------------------------------------------------
// 6) gather: out[col] = dinv[col]*( dinv[col]*xw[col] + Σ dinv[row]*(bd/bm)*xw[row] ) + bias
// ---------------------------------------------------------------------------
__global__ void __launch_bounds__(256) k_agg(const float* __restrict__ bias,
                                             float* __restrict__ out) {
    int wg   = (blockIdx.x * blockDim.x + threadIdx.x) >> 5;
    int lane = threadIdx.x & 31;
    if (wg >= CM) return;

    const float4* xw4 = (const float4*)g_xw;
    float dc  = g_dinv[wg];
    float ibm = 1.0f / __uint_as_float(g_bdmax_bits);
    int   deg = min(g_cnt[wg], CAP);

    float4 xv = __ldg(xw4 + (size_t)wg * 32 + lane);
    float4 acc;
    acc.x = dc * xv.x; acc.y = dc * xv.y; acc.z = dc * xv.z; acc.w = dc * xv.w;

    const int2* r = g_rec + (size_t)wg * CAP;
    for (int e0 = 0; e0 < deg; e0 += 32) {
        int idx = e0 + lane;
        int2 rc = make_int2(0, 0);
        if (idx < deg) rc = __ldg(r + idx);
        int nv = min(32, deg - e0);
        for (int j = 0; j < nv; j++) {
            int   row = __shfl_sync(0xffffffffu, rc.x, j);
            float bdv = __int_as_float(__shfl_sync(0xffffffffu, rc.y, j));
            float w2  = __ldg(&g_dinv[row]) * (bdv * ibm);
            float4 v  = __ldg(xw4 + (size_t)row * 32 + lane);
            acc.x += w2 * v.x; acc.y += w2 * v.y;
            acc.z += w2 * v.z; acc.w += w2 * v.w;
        }
    }

    float4 b4 = __ldg(((const float4*)bias) + lane);
    float4 o;
    o.x = dc * acc.x + b4.x;
    o.y = dc * acc.y + b4.y;
    o.z = dc * acc.z + b4.z;
    o.w = dc * acc.w + b4.w;
    ((float4*)out)[(size_t)wg * 32 + lane] = o;
}

// ---------------------------------------------------------------------------
// Launch
// ---------------------------------------------------------------------------
extern "C" void kernel_launch(void* const* d_in, const int* in_sizes, int n_in,
                              void* d_out, int out_size) {
    const float* x    = (const float*)d_in[0];
    const int*   ei   = (const int*)d_in[1];
    const float* bd   = (const float*)d_in[2];
    const float* Wm   = (const float*)d_in[3];
    const float* bias = (const float*)d_in[4];
    float*       out  = (float*)d_out;
    (void)in_sizes; (void)n_in; (void)out_size;

    cudaFuncSetAttribute(k_gemm, cudaFuncAttributeMaxDynamicSharedMemorySize, SM_TOT);

    k_init <<<(CM + 255) / 256, 256>>>();
    k_bdmax<<<1024, 256>>>(ei, bd);
    k_build<<<(CE + 255) / 256, 256>>>(ei, bd);
    k_dinv <<<(CM + 255) / 256, 256>>>();
    k_gemm <<<CM / 128, 256, SM_TOT>>>(x, Wm);
    k_agg  <<<(CM * 32 + 255) / 256, 256>>>(bias, out);
}

// round 6
// speedup vs baseline: 2.7329x; 1.2765x over previous
#include <cuda_runtime.h>
#include <cuda_bf16.h>
#include <cstdint>

// Problem constants (fixed by the dataset)
#define CS   256
#define CN   558
#define CB2  8192
#define CF   128
#define CM   (CS * CN)      // 142848
#define CE   (CS * CB2)     // 2097152
#define CAP  128            // CSR capacity per destination (in-degree ~11)

// ---------------------------------------------------------------------------
// Scratch
// ---------------------------------------------------------------------------
__device__ float    g_xw[(size_t)CM * CF];
__device__ float    g_deg[CM];                 // raw sum of bd over in-edges
__device__ float    g_dinv[CM];
__device__ int      g_cnt[CM];
__device__ int2     g_rec[(size_t)CM * CAP];   // {row, bits(bd)}
__device__ unsigned g_bdmax_bits;
__device__ uint4    g_wh4[2048];               // W hi plane, swizzled (32KB)
__device__ uint4    g_wl4[2048];               // W lo plane, swizzled (32KB)

// ---------------------------------------------------------------------------
// helpers
// ---------------------------------------------------------------------------
__device__ __forceinline__ unsigned smem_u32(const void* p) {
    unsigned a;
    asm("{ .reg .u64 t; cvta.to.shared.u64 t, %1; cvt.u32.u64 %0, t; }" : "=r"(a) : "l"(p));
    return a;
}
__device__ __forceinline__ uint4 ldsm4(unsigned addr) {
    uint4 v;
    asm volatile("ldmatrix.sync.aligned.m8n8.x4.shared.b16 {%0,%1,%2,%3}, [%4];"
                 : "=r"(v.x), "=r"(v.y), "=r"(v.z), "=r"(v.w) : "r"(addr));
    return v;
}
__device__ __forceinline__ void mma_bf16(float* d, uint4 a, unsigned b0, unsigned b1) {
    asm volatile(
        "mma.sync.aligned.m16n8k16.row.col.f32.bf16.bf16.f32 "
        "{%0,%1,%2,%3}, {%4,%5,%6,%7}, {%8,%9}, {%0,%1,%2,%3};"
        : "+f"(d[0]), "+f"(d[1]), "+f"(d[2]), "+f"(d[3])
        : "r"(a.x), "r"(a.y), "r"(a.z), "r"(a.w), "r"(b0), "r"(b1));
}
// swizzled byte offset within a (rows x 128)-bf16 plane (256B rows, 16B chunks)
__device__ __forceinline__ int swz(int r, int chunk) {
    return r * 256 + ((chunk ^ (r & 7)) << 4);
}

// ---------------------------------------------------------------------------
// 1) init
// ---------------------------------------------------------------------------
__global__ void k_init() {
    int i = blockIdx.x * blockDim.x + threadIdx.x;
    if (i == 0) g_bdmax_bits = 0u;
    if (i < CM) { g_deg[i] = 0.0f; g_cnt[i] = 0; }
}

// ---------------------------------------------------------------------------
// 2) W prep: bf16 hi/lo split of W into swizzled planes (one-time, tiny)
// ---------------------------------------------------------------------------
__global__ void k_wprep(const float* __restrict__ Wm) {
    int p = blockIdx.x * blockDim.x + threadIdx.x;   // 0 .. 128*64-1 (pairs)
    if (p >= 128 * 64) return;
    int r  = p >> 6;
    int kp = p & 63;
    float2 f = __ldg((const float2*)Wm + (size_t)r * 64 + kp);
    __nv_bfloat16 h0 = __float2bfloat16_rn(f.x);
    __nv_bfloat16 h1 = __float2bfloat16_rn(f.y);
    __nv_bfloat16 l0 = __float2bfloat16_rn(f.x - __bfloat162float(h0));
    __nv_bfloat16 l1 = __float2bfloat16_rn(f.y - __bfloat162float(h1));
    unsigned hh = ((unsigned)__bfloat16_as_ushort(h1) << 16) | __bfloat16_as_ushort(h0);
    unsigned ll = ((unsigned)__bfloat16_as_ushort(l1) << 16) | __bfloat16_as_ushort(l0);
    int byte = swz(r, kp >> 2) + ((kp & 3) << 2);
    *(unsigned*)((char*)g_wh4 + byte) = hh;
    *(unsigned*)((char*)g_wl4 + byte) = ll;
}

// ---------------------------------------------------------------------------
// 3) fused edge pass: bd_max block-reduce + deg[col] += bd + CSR fill
// ---------------------------------------------------------------------------
__global__ void k_build(const int* __restrict__ ei, const float* __restrict__ bd) {
    int g = blockIdx.x * blockDim.x + threadIdx.x;
    float v = 0.0f;
    if (g < CE) {
        int s   = g >> 13;
        int e   = g & (CB2 - 1);
        int src = __ldg(&ei[(size_t)s * 2 * CB2 + e]);
        int dst = __ldg(&ei[(size_t)s * 2 * CB2 + CB2 + e]);
        if (src != dst) {
            int row = s * CN + src;
            int col = s * CN + dst;
            float bdv = __ldg(&bd[g]);
            v = bdv;
            atomicAdd(&g_deg[col], bdv);
            int idx = atomicAdd(&g_cnt[col], 1);
            if (idx < CAP)
                g_rec[(size_t)col * CAP + idx] = make_int2(row, __float_as_int(bdv));
        }
    }
    // block max -> one atomicMax per block
    #pragma unroll
    for (int o = 16; o > 0; o >>= 1)
        v = fmaxf(v, __shfl_xor_sync(0xffffffffu, v, o));
    __shared__ float sm[8];
    int lane = threadIdx.x & 31, wid = threadIdx.x >> 5;
    if (lane == 0) sm[wid] = v;
    __syncthreads();
    if (wid == 0) {
        v = (lane < 8) ? sm[lane] : 0.0f;
        #pragma unroll
        for (int o = 4; o > 0; o >>= 1)
            v = fmaxf(v, __shfl_xor_sync(0xffffffffu, v, o));
        if (lane == 0) atomicMax(&g_bdmax_bits, __float_as_uint(v));
    }
}

// ---------------------------------------------------------------------------
// 4) dinv = rsqrt(1 + deg/bd_max)
// ---------------------------------------------------------------------------
__global__ void k_dinv() {
    int i = blockIdx.x * blockDim.x + threadIdx.x;
    if (i >= CM) return;
    float bm = __uint_as_float(g_bdmax_bits);
    g_dinv[i] = rsqrtf(1.0f + g_deg[i] / bm);
}

// ---------------------------------------------------------------------------
// 5) xw = x @ W^T via mma.sync bf16, 3-term split.
//    CTA = 64 rows, 128 threads (4 warps), 96KB smem -> 2 CTAs/SM.
// ---------------------------------------------------------------------------
#define SM_AH 0
#define SM_AL 16384
#define SM_WH 32768
#define SM_WL 65536
#define SM_TOT 98304

__global__ void __launch_bounds__(128) k_gemm(const float* __restrict__ x) {
    extern __shared__ char smem[];
    int tid = threadIdx.x, wid = tid >> 5, lane = tid & 31;
    size_t m0 = (size_t)blockIdx.x * 64;

    // copy precomputed W planes (64KB) from L2
    {
        uint4* dWh = (uint4*)(smem + SM_WH);
        uint4* dWl = (uint4*)(smem + SM_WL);
        #pragma unroll
        for (int i = 0; i < 16; i++) {
            dWh[tid + i * 128] = g_wh4[tid + i * 128];
            dWl[tid + i * 128] = g_wl4[tid + i * 128];
        }
    }
    // convert 64 rows of A to bf16 hi/lo planes
    {
        char* th = smem + SM_AH;
        char* tl = smem + SM_AL;
        const float2* gx = (const float2*)(x + m0 * CF);
        #pragma unroll
        for (int t = 0; t < 32; t++) {
            int p  = tid + t * 128;          // 0 .. 4095
            int r  = p >> 6;
            int kp = p & 63;
            float2 f = __ldg(gx + (size_t)r * 64 + kp);
            __nv_bfloat16 h0 = __float2bfloat16_rn(f.x);
            __nv_bfloat16 h1 = __float2bfloat16_rn(f.y);
            __nv_bfloat16 l0 = __float2bfloat16_rn(f.x - __bfloat162float(h0));
            __nv_bfloat16 l1 = __float2bfloat16_rn(f.y - __bfloat162float(h1));
            unsigned hh = ((unsigned)__bfloat16_as_ushort(h1) << 16) | __bfloat16_as_ushort(h0);
            unsigned ll = ((unsigned)__bfloat16_as_ushort(l1) << 16) | __bfloat16_as_ushort(l0);
            int byte = swz(r, kp >> 2) + ((kp & 3) << 2);
            *(unsigned*)(th + byte) = hh;
            *(unsigned*)(tl + byte) = ll;
        }
    }
    __syncthreads();

    unsigned sAh = smem_u32(smem + SM_AH);
    unsigned sAl = smem_u32(smem + SM_AL);
    unsigned sWh = smem_u32(smem + SM_WH);
    unsigned sWl = smem_u32(smem + SM_WL);

    int rbase = wid * 16;
    float acc[16][4];
    #pragma unroll
    for (int j = 0; j < 16; j++)
        #pragma unroll
        for (int c = 0; c < 4; c++) acc[j][c] = 0.0f;

    int am = lane >> 3;
    int ar = rbase + ((am & 1) << 3) + (lane & 7);
    int ac_off = am >> 1;
    int bm_ = lane >> 3;
    int br_off = ((bm_ >> 1) << 3) + (lane & 7);
    int bc_off = bm_ & 1;

    #pragma unroll
    for (int ks = 0; ks < 8; ks++) {
        uint4 ah = ldsm4(sAh + swz(ar, ks * 2 + ac_off));
        uint4 al = ldsm4(sAl + swz(ar, ks * 2 + ac_off));
        #pragma unroll
        for (int i = 0; i < 8; i++) {
            int brow = i * 16 + br_off;
            uint4 bh = ldsm4(sWh + swz(brow, ks * 2 + bc_off));
            mma_bf16(acc[2 * i],     ah, bh.x, bh.y);
            mma_bf16(acc[2 * i + 1], ah, bh.z, bh.w);
            mma_bf16(acc[2 * i],     al, bh.x, bh.y);
            mma_bf16(acc[2 * i + 1], al, bh.z, bh.w);
            uint4 bl = ldsm4(sWl + swz(brow, ks * 2 + bc_off));
            mma_bf16(acc[2 * i],     ah, bl.x, bl.y);
            mma_bf16(acc[2 * i + 1], ah, bl.z, bl.w);
        }
    }

    int erow = rbase + (lane >> 2);
    int ecol = (lane & 3) * 2;
    #pragma unroll
    for (int j = 0; j < 16; j++) {
        float* p0 = g_xw + (m0 + erow) * CF + j * 8 + ecol;
        p0[0] = acc[j][0];
        p0[1] = acc[j][1];
        float* p1 = p0 + 8 * CF;
        p1[0] = acc[j][2];
        p1[1] = acc[j][3];
    }
}

// ---------------------------------------------------------------------------
// 6) gather: out[col] = dinv[col]*( dinv[col]*xw[col] + Σ dinv[row]*(bd/bm)*xw[row] ) + bias
// ---------------------------------------------------------------------------
__global__ void __launch_bounds__(256) k_agg(const float* __restrict__ bias,
                                             float* __restrict__ out) {
    int wg   = (blockIdx.x * blockDim.x + threadIdx.x) >> 5;
    int lane = threadIdx.x & 31;
    if (wg >= CM) return;

    const float4* xw4 = (const float4*)g_xw;
    float dc  = g_dinv[wg];
    float ibm = 1.0f / __uint_as_float(g_bdmax_bits);
    int   deg = min(g_cnt[wg], CAP);

    float4 xv = __ldg(xw4 + (size_t)wg * 32 + lane);
    float4 acc;
    acc.x = dc * xv.x; acc.y = dc * xv.y; acc.z = dc * xv.z; acc.w = dc * xv.w;

    const int2* r = g_rec + (size_t)wg * CAP;
    for (int e0 = 0; e0 < deg; e0 += 32) {
        int idx = e0 + lane;
        int2 rc = make_int2(0, 0);
        if (idx < deg) rc = __ldg(r + idx);
        int nv = min(32, deg - e0);
        for (int j = 0; j < nv; j++) {
            int   row = __shfl_sync(0xffffffffu, rc.x, j);
            float bdv = __int_as_float(__shfl_sync(0xffffffffu, rc.y, j));
            float w2  = __ldg(&g_dinv[row]) * (bdv * ibm);
            float4 v  = __ldg(xw4 + (size_t)row * 32 + lane);
            acc.x += w2 * v.x; acc.y += w2 * v.y;
            acc.z += w2 * v.z; acc.w += w2 * v.w;
        }
    }

    float4 b4 = __ldg(((const float4*)bias) + lane);
    float4 o;
    o.x = dc * acc.x + b4.x;
    o.y = dc * acc.y + b4.y;
    o.z = dc * acc.z + b4.z;
    o.w = dc * acc.w + b4.w;
    ((float4*)out)[(size_t)wg * 32 + lane] = o;
}

// ---------------------------------------------------------------------------
// Launch
// ---------------------------------------------------------------------------
extern "C" void kernel_launch(void* const* d_in, const int* in_sizes, int n_in,
                              void* d_out, int out_size) {
    const float* x    = (const float*)d_in[0];
    const int*   ei   = (const int*)d_in[1];
    const float* bd   = (const float*)d_in[2];
    const float* Wm   = (const float*)d_in[3];
    const float* bias = (const float*)d_in[4];
    float*       out  = (float*)d_out;
    (void)in_sizes; (void)n_in; (void)out_size;

    cudaFuncSetAttribute(k_gemm, cudaFuncAttributeMaxDynamicSharedMemorySize, SM_TOT);

    k_init <<<(CM + 255) / 256, 256>>>();
    k_wprep<<<32, 256>>>(Wm);
    k_build<<<(CE + 255) / 256, 256>>>(ei, bd);
    k_dinv <<<(CM + 255) / 256, 256>>>();
    k_gemm <<<CM / 64, 128, SM_TOT>>>(x);
    k_agg  <<<(CM * 32 + 255) / 256, 256>>>(bias, out);
}